// round 12
// baseline (speedup 1.0000x reference)
#include <cuda_runtime.h>
#include <math.h>

#define H    64
#define G    192      // 3*H
#define HIDD 128
#define APP  512
#define TSTEPS 16
#define BMAX 131072

#define ROWS_A 64     // rows per GRU CTA
#define TPB_A  512
#define TPB_B  512
#define HROW   68     // padded h row stride (floats)

typedef unsigned long long ull;

// ---- device scratch ----
__device__ __align__(16) float g_M1[HIDD * APP];      // Wf_L @ Wa   [128,512]
__device__ __align__(16) float g_M2[HIDD * H];        // Wf_R @ Wt   [128,64]
__device__ __align__(16) float g_c [HIDD];            // Wf_L@ba + Wf_R@bt + bf
__device__ __align__(16) float g_Hlast[(size_t)BMAX * H];  // GRU last hidden

// ---- packed f32x2 helpers ----
__device__ __forceinline__ void fma2(ull& d, ull a, ull b) {
    asm("fma.rn.f32x2 %0, %1, %2, %0;" : "+l"(d) : "l"(a), "l"(b));
}
__device__ __forceinline__ void unpack2(ull a, float& lo, float& hi) {
    asm("mov.b64 {%0, %1}, %2;" : "=f"(lo), "=f"(hi) : "l"(a));
}
__device__ __forceinline__ ull pack_dup(float v) {
    ull r; asm("mov.b64 %0, {%1, %1};" : "=l"(r) : "f"(v)); return r;
}
__device__ __forceinline__ float hsum2(ull a) {
    float lo, hi; unpack2(a, lo, hi); return lo + hi;
}
__device__ __forceinline__ float tanh_hw(float x) {
    float r; asm("tanh.approx.f32 %0, %1;" : "=f"(r) : "f"(x)); return r;
}
__device__ __forceinline__ float sigmoid_hw(float x) {
    return fmaf(0.5f, tanh_hw(0.5f * x), 0.5f);
}

// ============================================================
// Kernel C: fold projection matrices (once per launch)
// ============================================================
__global__ void precompute_kernel(const float* __restrict__ Wt, const float* __restrict__ bt,
                                  const float* __restrict__ Wa, const float* __restrict__ ba,
                                  const float* __restrict__ Wf, const float* __restrict__ bf) {
    int bid = blockIdx.x, t = threadIdx.x;
    if (bid < 256) {
        int gt = bid * 256 + t;
        int o = gt >> 9, k = gt & 511;
        const float* wfo = Wf + o * (2 * HIDD);
        float a0 = 0.f, a1 = 0.f, a2 = 0.f, a3 = 0.f;
        #pragma unroll 4
        for (int c = 0; c < HIDD; c += 4) {
            a0 = fmaf(wfo[c+0], Wa[(size_t)(c+0) * APP + k], a0);
            a1 = fmaf(wfo[c+1], Wa[(size_t)(c+1) * APP + k], a1);
            a2 = fmaf(wfo[c+2], Wa[(size_t)(c+2) * APP + k], a2);
            a3 = fmaf(wfo[c+3], Wa[(size_t)(c+3) * APP + k], a3);
        }
        g_M1[(size_t)o * APP + k] = (a0 + a1) + (a2 + a3);
    } else if (bid < 288) {
        int gt = (bid - 256) * 256 + t;
        int o = gt >> 6, k = gt & 63;
        const float* wfo = Wf + o * (2 * HIDD) + HIDD;
        float a0 = 0.f, a1 = 0.f, a2 = 0.f, a3 = 0.f;
        #pragma unroll 4
        for (int c = 0; c < HIDD; c += 4) {
            a0 = fmaf(wfo[c+0], Wt[(c+0) * H + k], a0);
            a1 = fmaf(wfo[c+1], Wt[(c+1) * H + k], a1);
            a2 = fmaf(wfo[c+2], Wt[(c+2) * H + k], a2);
            a3 = fmaf(wfo[c+3], Wt[(c+3) * H + k], a3);
        }
        g_M2[o * H + k] = (a0 + a1) + (a2 + a3);
    } else {
        if (t < HIDD) {
            const float* wfo = Wf + t * (2 * HIDD);
            float acc = bf[t];
            for (int c = 0; c < HIDD; ++c) acc = fmaf(wfo[c], ba[c], acc);
            for (int c = 0; c < HIDD; ++c) acc = fmaf(wfo[HIDD + c], bt[c], acc);
            g_c[t] = acc;
        }
    }
}

// ============================================================
// Kernel A: GRU as per-timestep tile-GEMM. 512 threads.
// tc = tid&15 (col group: cols tc*4..+3 of each gate), tr = tid>>4 -> 2 rows.
// Thread tile: 2 rows x 12 cols, ~56 regs -> spill-free at 64-reg cap.
// 2 CTAs/SM (32 warps) = 8 warps/SMSP.
// ============================================================
#define SMEM_GRU (49152 + ROWS_A*HROW*4 + 640*4)

__global__ __launch_bounds__(TPB_A, 2)
void gru_kernel(const float* __restrict__ centroid,
                const float* __restrict__ W_ih, const float* __restrict__ W_hh,
                const float* __restrict__ b_ih, const float* __restrict__ b_hh,
                int B) {
    extern __shared__ char sm[];
    float* Wsm  = (float*)sm;                              // [64][192] W_hh^T
    float* hsm  = (float*)(sm + 49152);                    // [64][HROW]
    float* sW0  = (float*)(sm + 49152 + ROWS_A*HROW*4);    // 192
    float* sW1  = sW0 + G;                                 // 192
    float* sBrz = sW1 + G;                                 // 128: b_ih+b_hh (r,z)
    float* sBin = sBrz + 128;                              // 64 : b_ih n
    float* sBhn = sBin + 64;                               // 64 : b_hh n

    int tid = threadIdx.x;
    int tc  = tid & 15, tr = tid >> 4;   // tr: 0..31
    int tc4 = tc * 4;
    int row0 = tr * 2;

    // ---- stage ----
    for (int idx = tid; idx < G * H; idx += TPB_A) {
        int c = idx >> 6, k = idx & 63;
        Wsm[k * G + c] = W_hh[idx];
    }
    for (int i = tid; i < 128; i += TPB_A) sBrz[i] = b_ih[i] + b_hh[i];
    if (tid < 64) { sBin[tid] = b_ih[128 + tid]; sBhn[tid] = b_hh[128 + tid]; }
    for (int i = tid; i < G; i += TPB_A) { sW0[i] = W_ih[2 * i]; sW1[i] = W_ih[2 * i + 1]; }
    for (int i = tid; i < ROWS_A * HROW; i += TPB_A) hsm[i] = 0.f;
    __syncthreads();

    long long rowgBase = (long long)blockIdx.x * ROWS_A;
    const float2* xp[2];
    #pragma unroll
    for (int rr = 0; rr < 2; ++rr) {
        long long rg = rowgBase + row0 + rr;
        xp[rr] = (const float2*)centroid + (rg < (long long)B ? rg : 0) * TSTEPS;
    }

    float hnew[2][4];
    #pragma unroll
    for (int rr = 0; rr < 2; ++rr)
        #pragma unroll
        for (int jj = 0; jj < 4; ++jj) hnew[rr][jj] = 0.f;

    #pragma unroll 1
    for (int t = 0; t < TSTEPS; ++t) {
        ull acc[2][6];
        #pragma unroll
        for (int rr = 0; rr < 2; ++rr)
            #pragma unroll
            for (int p = 0; p < 6; ++p) acc[rr][p] = 0ULL;

        #pragma unroll 4
        for (int k = 0; k < H; ++k) {
            ull h0 = pack_dup(hsm[(row0 + 0) * HROW + k]);
            ull h1 = pack_dup(hsm[(row0 + 1) * HROW + k]);
            #pragma unroll
            for (int g = 0; g < 3; ++g) {
                ulonglong2 w = *(const ulonglong2*)(Wsm + k * G + g * 64 + tc4);
                fma2(acc[0][g * 2 + 0], w.x, h0);
                fma2(acc[0][g * 2 + 1], w.y, h0);
                fma2(acc[1][g * 2 + 0], w.x, h1);
                fma2(acc[1][g * 2 + 1], w.y, h1);
            }
        }

        // ---- gate phase (HW tanh; reads old h, pre-barrier) ----
        #pragma unroll
        for (int rr = 0; rr < 2; ++rr) {
            float2 xt = xp[rr][t];
            float gr[4], gz[4], gn[4];
            unpack2(acc[rr][0], gr[0], gr[1]); unpack2(acc[rr][1], gr[2], gr[3]);
            unpack2(acc[rr][2], gz[0], gz[1]); unpack2(acc[rr][3], gz[2], gz[3]);
            unpack2(acc[rr][4], gn[0], gn[1]); unpack2(acc[rr][5], gn[2], gn[3]);
            #pragma unroll
            for (int jj = 0; jj < 4; ++jj) {
                int j = tc4 + jj;
                float xr = fmaf(sW0[j],       xt.x, fmaf(sW1[j],       xt.y, sBrz[j]));
                float xz = fmaf(sW0[64 + j],  xt.x, fmaf(sW1[64 + j],  xt.y, sBrz[64 + j]));
                float xn = fmaf(sW0[128 + j], xt.x, fmaf(sW1[128 + j], xt.y, sBin[j]));
                float r  = sigmoid_hw(xr + gr[jj]);
                float z  = sigmoid_hw(xz + gz[jj]);
                float hn = gn[jj] + sBhn[j];
                float n  = tanh_hw(fmaf(r, hn, xn));
                float ho = hsm[(row0 + rr) * HROW + j];
                hnew[rr][jj] = n + z * (ho - n);
            }
        }
        __syncthreads();   // all reads of h_t done
        #pragma unroll
        for (int rr = 0; rr < 2; ++rr)
            *(float4*)&hsm[(row0 + rr) * HROW + tc4] =
                make_float4(hnew[rr][0], hnew[rr][1], hnew[rr][2], hnew[rr][3]);
        __syncthreads();   // h_{t+1} visible
    }

    #pragma unroll
    for (int rr = 0; rr < 2; ++rr) {
        long long rg = rowgBase + row0 + rr;
        if (rg < (long long)B)
            *(float4*)&g_Hlast[rg * H + tc4] =
                make_float4(hnew[rr][0], hnew[rr][1], hnew[rr][2], hnew[rr][3]);
    }
}

// ============================================================
// Kernel B: out = gelu(M1 @ app + M2 @ h_last + c)
// CTA: 128 rows x 64 outs (2 col-blocks per 128-out row). 512 thr,
// thread tile 4x4, ~64 regs -> 2 CTAs/SM (8 warps/SMSP).
// Warp lane layout: rows (l&7)+8i+(w&3)*32, outs (l>>3)+4j+(w>>2)*16
// -> LDS dedup: 8 + 4 distinct addrs per k2.
// ============================================================
__global__ __launch_bounds__(TPB_B, 2)
void proj_kernel(const float* __restrict__ app, float* __restrict__ out, int B) {
    __shared__ ull sa[16 * HIDD];   // [k2][row] rows of app / h_last
    __shared__ ull sw[16 * 64];     // [k2][o]   rows of M1 / M2
    __shared__ float sC[64];

    int tid = threadIdx.x;
    int rowblk = blockIdx.x >> 1;
    int colbase = (blockIdx.x & 1) * 64;
    long long row0 = (long long)rowblk * HIDD;

    // loader roles
    int lr = tid & 127;        // row loader (app/h_last)
    int kg = tid >> 7;         // 0..3 : k-group of 8 floats (4 k2)
    int lo = tid & 63;         // weight-out loader
    int kgw = tid >> 6;        // 0..7 : k-group of 4 floats (2 k2)

    // compute roles
    int w = tid >> 5, l = tid & 31;
    int rbase = (w & 3) * 32 + (l & 7);       // +8*i
    int obase = (w >> 2) * 16 + (l >> 3);     // +4*j

    if (tid < 64) sC[tid] = g_c[colbase + tid];

    ull acc[4][4];
    #pragma unroll
    for (int i = 0; i < 4; ++i)
        #pragma unroll
        for (int j = 0; j < 4; ++j) acc[i][j] = 0ULL;

    long long ar = row0 + lr;
    bool aval = (ar < (long long)B);
    const ulonglong2* aptr = (const ulonglong2*)(app + (aval ? ar : 0) * APP);
    const ulonglong2* hptr = (const ulonglong2*)(g_Hlast + (aval ? ar : 0) * H);
    const float* wrow1 = g_M1 + (size_t)(colbase + lo) * APP;
    const float* wrow2 = g_M2 + (colbase + lo) * H;

    // 18 K-tiles: 16 over appearance (K=512), 2 over h_last (K=64)
    #pragma unroll 1
    for (int kt = 0; kt < 18; ++kt) {
        ulonglong2 zz; zz.x = 0ULL; zz.y = 0ULL;
        ulonglong2 va0, va1, vw;
        if (kt < 16) {
            int kof = kt * 32 + kg * 8;
            va0 = aval ? aptr[kof / 4] : zz;
            va1 = aval ? aptr[kof / 4 + 1] : zz;
            vw  = ((const ulonglong2*)(wrow1 + kt * 32))[kgw];
        } else {
            int kof = (kt - 16) * 32 + kg * 8;
            va0 = aval ? hptr[kof / 4] : zz;
            va1 = aval ? hptr[kof / 4 + 1] : zz;
            vw  = ((const ulonglong2*)(wrow2 + (kt - 16) * 32))[kgw];
        }
        int k2b = kg * 4;
        sa[(k2b + 0) * HIDD + lr] = va0.x;
        sa[(k2b + 1) * HIDD + lr] = va0.y;
        sa[(k2b + 2) * HIDD + lr] = va1.x;
        sa[(k2b + 3) * HIDD + lr] = va1.y;
        sw[(kgw * 2 + 0) * 64 + lo] = vw.x;
        sw[(kgw * 2 + 1) * 64 + lo] = vw.y;
        __syncthreads();

        #pragma unroll
        for (int k2 = 0; k2 < 16; ++k2) {
            ull a2[4], w2[4];
            #pragma unroll
            for (int i = 0; i < 4; ++i) a2[i] = sa[k2 * HIDD + rbase + 8 * i];
            #pragma unroll
            for (int j = 0; j < 4; ++j) w2[j] = sw[k2 * 64 + obase + 4 * j];
            #pragma unroll
            for (int i = 0; i < 4; ++i)
                #pragma unroll
                for (int j = 0; j < 4; ++j) fma2(acc[i][j], a2[i], w2[j]);
        }
        __syncthreads();
    }

    #pragma unroll
    for (int i = 0; i < 4; ++i) {
        long long r = row0 + rbase + 8 * i;
        if (r < (long long)B) {
            #pragma unroll
            for (int j = 0; j < 4; ++j) {
                int ol = obase + 4 * j;
                float v = hsum2(acc[i][j]) + sC[ol];
                out[r * HIDD + colbase + ol] =
                    0.5f * v * (1.f + erff(v * 0.7071067811865476f));
            }
        }
    }
}

// ============================================================
extern "C" void kernel_launch(void* const* d_in, const int* in_sizes, int n_in,
                              void* d_out, int out_size) {
    const float* app  = (const float*)d_in[0];
    const float* cen  = (const float*)d_in[1];
    const float* W_ih = (const float*)d_in[2];
    const float* W_hh = (const float*)d_in[3];
    const float* b_ih = (const float*)d_in[4];
    const float* b_hh = (const float*)d_in[5];
    const float* Wt   = (const float*)d_in[6];
    const float* bt   = (const float*)d_in[7];
    const float* Wa   = (const float*)d_in[8];
    const float* ba   = (const float*)d_in[9];
    const float* Wf   = (const float*)d_in[10];
    const float* bf   = (const float*)d_in[11];
    float* out = (float*)d_out;

    int B = in_sizes[0] / APP;

    (void)cudaGetLastError();
    (void)cudaFuncSetAttribute(gru_kernel,
                               cudaFuncAttributeMaxDynamicSharedMemorySize, SMEM_GRU);

    precompute_kernel<<<289, 256>>>(Wt, bt, Wa, ba, Wf, bf);

    int gridA = (B + ROWS_A - 1) / ROWS_A;
    gru_kernel<<<gridA, TPB_A, SMEM_GRU>>>(cen, W_ih, W_hh, b_ih, b_hh, B);

    int gridB = ((B + HIDD - 1) / HIDD) * 2;
    proj_kernel<<<gridB, TPB_B>>>(app, out, B);
}

// round 13
// speedup vs baseline: 1.1199x; 1.1199x over previous
#include <cuda_runtime.h>
#include <math.h>

#define H    64
#define G    192      // 3*H
#define HIDD 128
#define APP  512
#define TSTEPS 16
#define BMAX 131072

#define ROWS_A 64     // rows per GRU CTA
#define TPB_A  256
#define TPB_B  512
#define HROW   68     // padded h row stride (floats)

typedef unsigned long long ull;

// ---- device scratch ----
__device__ __align__(16) float g_M1[HIDD * APP];      // Wf_L @ Wa   [128,512]
__device__ __align__(16) float g_M2[HIDD * H];        // Wf_R @ Wt   [128,64]
__device__ __align__(16) float g_c [HIDD];            // Wf_L@ba + Wf_R@bt + bf
__device__ __align__(16) float g_Hlast[(size_t)BMAX * H];  // GRU last hidden

// ---- packed f32x2 helpers ----
__device__ __forceinline__ void fma2(ull& d, ull a, ull b) {
    asm("fma.rn.f32x2 %0, %1, %2, %0;" : "+l"(d) : "l"(a), "l"(b));
}
__device__ __forceinline__ void unpack2(ull a, float& lo, float& hi) {
    asm("mov.b64 {%0, %1}, %2;" : "=f"(lo), "=f"(hi) : "l"(a));
}
__device__ __forceinline__ ull pack_dup(float v) {
    ull r; asm("mov.b64 %0, {%1, %1};" : "=l"(r) : "f"(v)); return r;
}
__device__ __forceinline__ float hsum2(ull a) {
    float lo, hi; unpack2(a, lo, hi); return lo + hi;
}
__device__ __forceinline__ float tanh_hw(float x) {
    float r; asm("tanh.approx.f32 %0, %1;" : "=f"(r) : "f"(x)); return r;
}
__device__ __forceinline__ float sigmoid_hw(float x) {
    return fmaf(0.5f, tanh_hw(0.5f * x), 0.5f);
}

// ============================================================
// Kernel C: fold projection matrices (once per launch)
// ============================================================
__global__ void precompute_kernel(const float* __restrict__ Wt, const float* __restrict__ bt,
                                  const float* __restrict__ Wa, const float* __restrict__ ba,
                                  const float* __restrict__ Wf, const float* __restrict__ bf) {
    int bid = blockIdx.x, t = threadIdx.x;
    if (bid < 256) {
        int gt = bid * 256 + t;
        int o = gt >> 9, k = gt & 511;
        const float* wfo = Wf + o * (2 * HIDD);
        float a0 = 0.f, a1 = 0.f, a2 = 0.f, a3 = 0.f;
        #pragma unroll 4
        for (int c = 0; c < HIDD; c += 4) {
            a0 = fmaf(wfo[c+0], Wa[(size_t)(c+0) * APP + k], a0);
            a1 = fmaf(wfo[c+1], Wa[(size_t)(c+1) * APP + k], a1);
            a2 = fmaf(wfo[c+2], Wa[(size_t)(c+2) * APP + k], a2);
            a3 = fmaf(wfo[c+3], Wa[(size_t)(c+3) * APP + k], a3);
        }
        g_M1[(size_t)o * APP + k] = (a0 + a1) + (a2 + a3);
    } else if (bid < 288) {
        int gt = (bid - 256) * 256 + t;
        int o = gt >> 6, k = gt & 63;
        const float* wfo = Wf + o * (2 * HIDD) + HIDD;
        float a0 = 0.f, a1 = 0.f, a2 = 0.f, a3 = 0.f;
        #pragma unroll 4
        for (int c = 0; c < HIDD; c += 4) {
            a0 = fmaf(wfo[c+0], Wt[(c+0) * H + k], a0);
            a1 = fmaf(wfo[c+1], Wt[(c+1) * H + k], a1);
            a2 = fmaf(wfo[c+2], Wt[(c+2) * H + k], a2);
            a3 = fmaf(wfo[c+3], Wt[(c+3) * H + k], a3);
        }
        g_M2[o * H + k] = (a0 + a1) + (a2 + a3);
    } else {
        if (t < HIDD) {
            const float* wfo = Wf + t * (2 * HIDD);
            float acc = bf[t];
            for (int c = 0; c < HIDD; ++c) acc = fmaf(wfo[c], ba[c], acc);
            for (int c = 0; c < HIDD; ++c) acc = fmaf(wfo[HIDD + c], bt[c], acc);
            g_c[t] = acc;
        }
    }
}

// ============================================================
// Kernel A: GRU as per-timestep tile-GEMM (R11 shape: 256 thr, 4 rows/thread,
// occ 3 -> 6 warps/SMSP) + HW tanh gates + float2 h-loads.
// tc = tid&15 (cols tc*4..+3 of each gate), tr = tid>>4 -> 4 rows.
// ============================================================
#define SMEM_GRU (49152 + ROWS_A*HROW*4 + 640*4)

__global__ __launch_bounds__(TPB_A, 3)
void gru_kernel(const float* __restrict__ centroid,
                const float* __restrict__ W_ih, const float* __restrict__ W_hh,
                const float* __restrict__ b_ih, const float* __restrict__ b_hh,
                int B) {
    extern __shared__ char sm[];
    float* Wsm  = (float*)sm;                              // [64][192] W_hh^T
    float* hsm  = (float*)(sm + 49152);                    // [64][HROW]
    float* sW0  = (float*)(sm + 49152 + ROWS_A*HROW*4);    // 192
    float* sW1  = sW0 + G;                                 // 192
    float* sBrz = sW1 + G;                                 // 128: b_ih+b_hh (r,z)
    float* sBin = sBrz + 128;                              // 64 : b_ih n
    float* sBhn = sBin + 64;                               // 64 : b_hh n

    int tid = threadIdx.x;
    int tc  = tid & 15, tr = tid >> 4;
    int tc4 = tc * 4;
    int row0 = tr * 4;

    // ---- stage: W_hh transposed to [k][192], biases, W_ih, zero h ----
    for (int idx = tid; idx < G * H; idx += TPB_A) {
        int c = idx >> 6, k = idx & 63;          // W_hh[c][k], coalesced read
        Wsm[k * G + c] = W_hh[idx];
    }
    for (int i = tid; i < 128; i += TPB_A) sBrz[i] = b_ih[i] + b_hh[i];
    if (tid < 64) { sBin[tid] = b_ih[128 + tid]; sBhn[tid] = b_hh[128 + tid]; }
    for (int i = tid; i < G; i += TPB_A) { sW0[i] = W_ih[2 * i]; sW1[i] = W_ih[2 * i + 1]; }
    for (int i = tid; i < ROWS_A * HROW; i += TPB_A) hsm[i] = 0.f;
    __syncthreads();

    long long rowgBase = (long long)blockIdx.x * ROWS_A;
    const float2* xp[4];
    #pragma unroll
    for (int rr = 0; rr < 4; ++rr) {
        long long rg = rowgBase + row0 + rr;
        xp[rr] = (const float2*)centroid + (rg < (long long)B ? rg : 0) * TSTEPS;
    }

    float hnew[4][4];
    #pragma unroll
    for (int rr = 0; rr < 4; ++rr)
        #pragma unroll
        for (int jj = 0; jj < 4; ++jj) hnew[rr][jj] = 0.f;

    #pragma unroll 1
    for (int t = 0; t < TSTEPS; ++t) {
        // ---- GEMM phase ----
        ull acc[4][6];
        #pragma unroll
        for (int rr = 0; rr < 4; ++rr)
            #pragma unroll
            for (int p = 0; p < 6; ++p) acc[rr][p] = 0ULL;

        #pragma unroll 2
        for (int k2 = 0; k2 < 32; ++k2) {
            float2 hv[4];
            #pragma unroll
            for (int rr = 0; rr < 4; ++rr)
                hv[rr] = *(const float2*)&hsm[(row0 + rr) * HROW + k2 * 2];
            #pragma unroll
            for (int kk = 0; kk < 2; ++kk) {
                int k = k2 * 2 + kk;
                ull hh[4];
                #pragma unroll
                for (int rr = 0; rr < 4; ++rr)
                    hh[rr] = pack_dup(kk ? hv[rr].y : hv[rr].x);
                #pragma unroll
                for (int g = 0; g < 3; ++g) {
                    ulonglong2 w = *(const ulonglong2*)(Wsm + k * G + g * 64 + tc4);
                    #pragma unroll
                    for (int rr = 0; rr < 4; ++rr) {
                        fma2(acc[rr][g * 2 + 0], w.x, hh[rr]);
                        fma2(acc[rr][g * 2 + 1], w.y, hh[rr]);
                    }
                }
            }
        }

        // ---- gate phase (HW tanh; reads old h, pre-barrier) ----
        #pragma unroll
        for (int rr = 0; rr < 4; ++rr) {
            float2 xt = xp[rr][t];
            float gr[4], gz[4], gn[4];
            unpack2(acc[rr][0], gr[0], gr[1]); unpack2(acc[rr][1], gr[2], gr[3]);
            unpack2(acc[rr][2], gz[0], gz[1]); unpack2(acc[rr][3], gz[2], gz[3]);
            unpack2(acc[rr][4], gn[0], gn[1]); unpack2(acc[rr][5], gn[2], gn[3]);
            #pragma unroll
            for (int jj = 0; jj < 4; ++jj) {
                int j = tc4 + jj;
                float xr = fmaf(sW0[j],       xt.x, fmaf(sW1[j],       xt.y, sBrz[j]));
                float xz = fmaf(sW0[64 + j],  xt.x, fmaf(sW1[64 + j],  xt.y, sBrz[64 + j]));
                float xn = fmaf(sW0[128 + j], xt.x, fmaf(sW1[128 + j], xt.y, sBin[j]));
                float r  = sigmoid_hw(xr + gr[jj]);
                float z  = sigmoid_hw(xz + gz[jj]);
                float hn = gn[jj] + sBhn[j];
                float n  = tanh_hw(fmaf(r, hn, xn));
                float ho = hsm[(row0 + rr) * HROW + j];
                hnew[rr][jj] = n + z * (ho - n);
            }
        }
        __syncthreads();   // all reads of h_t done
        #pragma unroll
        for (int rr = 0; rr < 4; ++rr)
            *(float4*)&hsm[(row0 + rr) * HROW + tc4] =
                make_float4(hnew[rr][0], hnew[rr][1], hnew[rr][2], hnew[rr][3]);
        __syncthreads();   // h_{t+1} visible
    }

    #pragma unroll
    for (int rr = 0; rr < 4; ++rr) {
        long long rg = rowgBase + row0 + rr;
        if (rg < (long long)B)
            *(float4*)&g_Hlast[rg * H + tc4] =
                make_float4(hnew[rr][0], hnew[rr][1], hnew[rr][2], hnew[rr][3]);
    }
}

// ============================================================
// Kernel B (R12-proven): out = gelu(M1 @ app + M2 @ h_last + c)
// CTA: 128 rows x 64 outs. 512 thr, 4x4 tile, 2 CTAs/SM.
// ============================================================
__global__ __launch_bounds__(TPB_B, 2)
void proj_kernel(const float* __restrict__ app, float* __restrict__ out, int B) {
    __shared__ ull sa[16 * HIDD];   // [k2][row] rows of app / h_last
    __shared__ ull sw[16 * 64];     // [k2][o]   rows of M1 / M2
    __shared__ float sC[64];

    int tid = threadIdx.x;
    int rowblk = blockIdx.x >> 1;
    int colbase = (blockIdx.x & 1) * 64;
    long long row0 = (long long)rowblk * HIDD;

    // loader roles
    int lr = tid & 127;        // row loader (app/h_last)
    int kg = tid >> 7;         // 0..3 : k-group of 8 floats (4 k2)
    int lo = tid & 63;         // weight-out loader
    int kgw = tid >> 6;        // 0..7 : k-group of 4 floats (2 k2)

    // compute roles
    int w = tid >> 5, l = tid & 31;
    int rbase = (w & 3) * 32 + (l & 7);       // +8*i
    int obase = (w >> 2) * 16 + (l >> 3);     // +4*j

    if (tid < 64) sC[tid] = g_c[colbase + tid];

    ull acc[4][4];
    #pragma unroll
    for (int i = 0; i < 4; ++i)
        #pragma unroll
        for (int j = 0; j < 4; ++j) acc[i][j] = 0ULL;

    long long ar = row0 + lr;
    bool aval = (ar < (long long)B);
    const ulonglong2* aptr = (const ulonglong2*)(app + (aval ? ar : 0) * APP);
    const ulonglong2* hptr = (const ulonglong2*)(g_Hlast + (aval ? ar : 0) * H);
    const float* wrow1 = g_M1 + (size_t)(colbase + lo) * APP;
    const float* wrow2 = g_M2 + (colbase + lo) * H;

    // 18 K-tiles: 16 over appearance (K=512), 2 over h_last (K=64)
    #pragma unroll 1
    for (int kt = 0; kt < 18; ++kt) {
        ulonglong2 zz; zz.x = 0ULL; zz.y = 0ULL;
        ulonglong2 va0, va1, vw;
        if (kt < 16) {
            int kof = kt * 32 + kg * 8;
            va0 = aval ? aptr[kof / 4] : zz;
            va1 = aval ? aptr[kof / 4 + 1] : zz;
            vw  = ((const ulonglong2*)(wrow1 + kt * 32))[kgw];
        } else {
            int kof = (kt - 16) * 32 + kg * 8;
            va0 = aval ? hptr[kof / 4] : zz;
            va1 = aval ? hptr[kof / 4 + 1] : zz;
            vw  = ((const ulonglong2*)(wrow2 + (kt - 16) * 32))[kgw];
        }
        int k2b = kg * 4;
        sa[(k2b + 0) * HIDD + lr] = va0.x;
        sa[(k2b + 1) * HIDD + lr] = va0.y;
        sa[(k2b + 2) * HIDD + lr] = va1.x;
        sa[(k2b + 3) * HIDD + lr] = va1.y;
        sw[(kgw * 2 + 0) * 64 + lo] = vw.x;
        sw[(kgw * 2 + 1) * 64 + lo] = vw.y;
        __syncthreads();

        #pragma unroll
        for (int k2 = 0; k2 < 16; ++k2) {
            ull a2[4], w2[4];
            #pragma unroll
            for (int i = 0; i < 4; ++i) a2[i] = sa[k2 * HIDD + rbase + 8 * i];
            #pragma unroll
            for (int j = 0; j < 4; ++j) w2[j] = sw[k2 * 64 + obase + 4 * j];
            #pragma unroll
            for (int i = 0; i < 4; ++i)
                #pragma unroll
                for (int j = 0; j < 4; ++j) fma2(acc[i][j], a2[i], w2[j]);
        }
        __syncthreads();
    }

    #pragma unroll
    for (int i = 0; i < 4; ++i) {
        long long r = row0 + rbase + 8 * i;
        if (r < (long long)B) {
            #pragma unroll
            for (int j = 0; j < 4; ++j) {
                int ol = obase + 4 * j;
                float v = hsum2(acc[i][j]) + sC[ol];
                out[r * HIDD + colbase + ol] =
                    0.5f * v * (1.f + erff(v * 0.7071067811865476f));
            }
        }
    }
}

// ============================================================
extern "C" void kernel_launch(void* const* d_in, const int* in_sizes, int n_in,
                              void* d_out, int out_size) {
    const float* app  = (const float*)d_in[0];
    const float* cen  = (const float*)d_in[1];
    const float* W_ih = (const float*)d_in[2];
    const float* W_hh = (const float*)d_in[3];
    const float* b_ih = (const float*)d_in[4];
    const float* b_hh = (const float*)d_in[5];
    const float* Wt   = (const float*)d_in[6];
    const float* bt   = (const float*)d_in[7];
    const float* Wa   = (const float*)d_in[8];
    const float* ba   = (const float*)d_in[9];
    const float* Wf   = (const float*)d_in[10];
    const float* bf   = (const float*)d_in[11];
    float* out = (float*)d_out;

    int B = in_sizes[0] / APP;

    (void)cudaGetLastError();
    (void)cudaFuncSetAttribute(gru_kernel,
                               cudaFuncAttributeMaxDynamicSharedMemorySize, SMEM_GRU);

    precompute_kernel<<<289, 256>>>(Wt, bt, Wa, ba, Wf, bf);

    int gridA = (B + ROWS_A - 1) / ROWS_A;
    gru_kernel<<<gridA, TPB_A, SMEM_GRU>>>(cen, W_ih, W_hh, b_ih, b_hh, B);

    int gridB = ((B + HIDD - 1) / HIDD) * 2;
    proj_kernel<<<gridB, TPB_B>>>(app, out, B);
}

// round 14
// speedup vs baseline: 1.2509x; 1.1169x over previous
#include <cuda_runtime.h>
#include <math.h>

#define H    64
#define G    192      // 3*H
#define HIDD 128
#define APP  512
#define TSTEPS 16
#define BMAX 131072

#define ROWS_A 64     // rows per GRU CTA
#define TPB_A  256
#define TPB_B  512
#define HROW   68     // padded h row stride (floats)

typedef unsigned long long ull;

// ---- device scratch ----
__device__ __align__(16) float g_M1[HIDD * APP];      // Wf_L @ Wa   [128,512]
__device__ __align__(16) float g_M2[HIDD * H];        // Wf_R @ Wt   [128,64]
__device__ __align__(16) float g_c [HIDD];            // Wf_L@ba + Wf_R@bt + bf
__device__ __align__(16) float g_Hlast[(size_t)BMAX * H];  // GRU last hidden

// ---- packed f32x2 helpers ----
__device__ __forceinline__ void fma2(ull& d, ull a, ull b) {
    asm("fma.rn.f32x2 %0, %1, %2, %0;" : "+l"(d) : "l"(a), "l"(b));
}
__device__ __forceinline__ void unpack2(ull a, float& lo, float& hi) {
    asm("mov.b64 {%0, %1}, %2;" : "=f"(lo), "=f"(hi) : "l"(a));
}
__device__ __forceinline__ ull pack_dup(float v) {
    ull r; asm("mov.b64 %0, {%1, %1};" : "=l"(r) : "f"(v)); return r;
}
__device__ __forceinline__ float hsum2(ull a) {
    float lo, hi; unpack2(a, lo, hi); return lo + hi;
}
__device__ __forceinline__ float tanh_hw(float x) {
    float r; asm("tanh.approx.f32 %0, %1;" : "=f"(r) : "f"(x)); return r;
}
__device__ __forceinline__ float sigmoid_hw(float x) {
    return fmaf(0.5f, tanh_hw(0.5f * x), 0.5f);
}

// ============================================================
// Kernel C: fold projection matrices (once per launch)
// ============================================================
__global__ void precompute_kernel(const float* __restrict__ Wt, const float* __restrict__ bt,
                                  const float* __restrict__ Wa, const float* __restrict__ ba,
                                  const float* __restrict__ Wf, const float* __restrict__ bf) {
    int bid = blockIdx.x, t = threadIdx.x;
    if (bid < 256) {
        int gt = bid * 256 + t;
        int o = gt >> 9, k = gt & 511;
        const float* wfo = Wf + o * (2 * HIDD);
        float a0 = 0.f, a1 = 0.f, a2 = 0.f, a3 = 0.f;
        #pragma unroll 4
        for (int c = 0; c < HIDD; c += 4) {
            a0 = fmaf(wfo[c+0], Wa[(size_t)(c+0) * APP + k], a0);
            a1 = fmaf(wfo[c+1], Wa[(size_t)(c+1) * APP + k], a1);
            a2 = fmaf(wfo[c+2], Wa[(size_t)(c+2) * APP + k], a2);
            a3 = fmaf(wfo[c+3], Wa[(size_t)(c+3) * APP + k], a3);
        }
        g_M1[(size_t)o * APP + k] = (a0 + a1) + (a2 + a3);
    } else if (bid < 288) {
        int gt = (bid - 256) * 256 + t;
        int o = gt >> 6, k = gt & 63;
        const float* wfo = Wf + o * (2 * HIDD) + HIDD;
        float a0 = 0.f, a1 = 0.f, a2 = 0.f, a3 = 0.f;
        #pragma unroll 4
        for (int c = 0; c < HIDD; c += 4) {
            a0 = fmaf(wfo[c+0], Wt[(c+0) * H + k], a0);
            a1 = fmaf(wfo[c+1], Wt[(c+1) * H + k], a1);
            a2 = fmaf(wfo[c+2], Wt[(c+2) * H + k], a2);
            a3 = fmaf(wfo[c+3], Wt[(c+3) * H + k], a3);
        }
        g_M2[o * H + k] = (a0 + a1) + (a2 + a3);
    } else {
        if (t < HIDD) {
            const float* wfo = Wf + t * (2 * HIDD);
            float acc = bf[t];
            for (int c = 0; c < HIDD; ++c) acc = fmaf(wfo[c], ba[c], acc);
            for (int c = 0; c < HIDD; ++c) acc = fmaf(wfo[HIDD + c], bt[c], acc);
            g_c[t] = acc;
        }
    }
}

// ============================================================
// Kernel A: GRU as per-timestep tile-GEMM — R11 shape verbatim
// (256 thr, 4 rows/thread, occ 3, scalar h loads, unroll 4),
// ONLY change: HW tanh/sigmoid gates.
// ============================================================
#define SMEM_GRU (49152 + ROWS_A*HROW*4 + 640*4)

__global__ __launch_bounds__(TPB_A, 3)
void gru_kernel(const float* __restrict__ centroid,
                const float* __restrict__ W_ih, const float* __restrict__ W_hh,
                const float* __restrict__ b_ih, const float* __restrict__ b_hh,
                int B) {
    extern __shared__ char sm[];
    float* Wsm  = (float*)sm;                              // [64][192] W_hh^T
    float* hsm  = (float*)(sm + 49152);                    // [64][HROW]
    float* sW0  = (float*)(sm + 49152 + ROWS_A*HROW*4);    // 192
    float* sW1  = sW0 + G;                                 // 192
    float* sBrz = sW1 + G;                                 // 128: b_ih+b_hh (r,z)
    float* sBin = sBrz + 128;                              // 64 : b_ih n
    float* sBhn = sBin + 64;                               // 64 : b_hh n

    int tid = threadIdx.x;
    int tc  = tid & 15, tr = tid >> 4;
    int tc4 = tc * 4;
    int row0 = tr * 4;

    // ---- stage: W_hh transposed to [k][192], biases, W_ih, zero h ----
    for (int idx = tid; idx < G * H; idx += TPB_A) {
        int c = idx >> 6, k = idx & 63;          // W_hh[c][k], coalesced read
        Wsm[k * G + c] = W_hh[idx];
    }
    for (int i = tid; i < 128; i += TPB_A) sBrz[i] = b_ih[i] + b_hh[i];
    if (tid < 64) { sBin[tid] = b_ih[128 + tid]; sBhn[tid] = b_hh[128 + tid]; }
    for (int i = tid; i < G; i += TPB_A) { sW0[i] = W_ih[2 * i]; sW1[i] = W_ih[2 * i + 1]; }
    for (int i = tid; i < ROWS_A * HROW; i += TPB_A) hsm[i] = 0.f;
    __syncthreads();

    long long rowgBase = (long long)blockIdx.x * ROWS_A;
    const float2* xp[4];
    #pragma unroll
    for (int rr = 0; rr < 4; ++rr) {
        long long rg = rowgBase + row0 + rr;
        xp[rr] = (const float2*)centroid + (rg < (long long)B ? rg : 0) * TSTEPS;
    }

    float hnew[4][4];
    #pragma unroll
    for (int rr = 0; rr < 4; ++rr)
        #pragma unroll
        for (int jj = 0; jj < 4; ++jj) hnew[rr][jj] = 0.f;

    #pragma unroll 1
    for (int t = 0; t < TSTEPS; ++t) {
        // ---- GEMM phase: acc[rr][g*2+p] accumulates col-pairs over k ----
        ull acc[4][6];
        #pragma unroll
        for (int rr = 0; rr < 4; ++rr)
            #pragma unroll
            for (int p = 0; p < 6; ++p) acc[rr][p] = 0ULL;

        #pragma unroll 4
        for (int k = 0; k < H; ++k) {
            ull hh[4];
            #pragma unroll
            for (int rr = 0; rr < 4; ++rr)
                hh[rr] = pack_dup(hsm[(row0 + rr) * HROW + k]);
            #pragma unroll
            for (int g = 0; g < 3; ++g) {
                ulonglong2 w = *(const ulonglong2*)(Wsm + k * G + g * 64 + tc4);
                #pragma unroll
                for (int rr = 0; rr < 4; ++rr) {
                    fma2(acc[rr][g * 2 + 0], w.x, hh[rr]);
                    fma2(acc[rr][g * 2 + 1], w.y, hh[rr]);
                }
            }
        }

        // ---- gate phase (HW tanh; reads old h, pre-barrier) ----
        #pragma unroll
        for (int rr = 0; rr < 4; ++rr) {
            float2 xt = xp[rr][t];
            float gr[4], gz[4], gn[4];
            unpack2(acc[rr][0], gr[0], gr[1]); unpack2(acc[rr][1], gr[2], gr[3]);
            unpack2(acc[rr][2], gz[0], gz[1]); unpack2(acc[rr][3], gz[2], gz[3]);
            unpack2(acc[rr][4], gn[0], gn[1]); unpack2(acc[rr][5], gn[2], gn[3]);
            #pragma unroll
            for (int jj = 0; jj < 4; ++jj) {
                int j = tc4 + jj;
                float xr = fmaf(sW0[j],       xt.x, fmaf(sW1[j],       xt.y, sBrz[j]));
                float xz = fmaf(sW0[64 + j],  xt.x, fmaf(sW1[64 + j],  xt.y, sBrz[64 + j]));
                float xn = fmaf(sW0[128 + j], xt.x, fmaf(sW1[128 + j], xt.y, sBin[j]));
                float r  = sigmoid_hw(xr + gr[jj]);
                float z  = sigmoid_hw(xz + gz[jj]);
                float hn = gn[jj] + sBhn[j];
                float n  = tanh_hw(fmaf(r, hn, xn));
                float ho = hsm[(row0 + rr) * HROW + j];
                hnew[rr][jj] = n + z * (ho - n);
            }
        }
        __syncthreads();   // all reads of h_t done
        #pragma unroll
        for (int rr = 0; rr < 4; ++rr)
            *(float4*)&hsm[(row0 + rr) * HROW + tc4] =
                make_float4(hnew[rr][0], hnew[rr][1], hnew[rr][2], hnew[rr][3]);
        __syncthreads();   // h_{t+1} visible
    }

    #pragma unroll
    for (int rr = 0; rr < 4; ++rr) {
        long long rg = rowgBase + row0 + rr;
        if (rg < (long long)B)
            *(float4*)&g_Hlast[rg * H + tc4] =
                make_float4(hnew[rr][0], hnew[rr][1], hnew[rr][2], hnew[rr][3]);
    }
}

// ============================================================
// Kernel B (R11-proven projA): out = gelu(M1 @ app + M2 @ h_last + c)
// CTA: 128 rows x 128 outs, 512 threads, 8x4 f32x2 microtiles
// ============================================================
__global__ __launch_bounds__(TPB_B, 1)
void proj_kernel(const float* __restrict__ app, float* __restrict__ out, int B) {
    __shared__ ull sa[16 * HIDD];   // [k2][row]
    __shared__ ull sw[16 * HIDD];   // [k2][o]
    __shared__ float sC[HIDD];

    int tid = threadIdx.x;
    long long row0 = (long long)blockIdx.x * HIDD;
    int lr = tid & 127;       // loader row / loader out
    int kg = tid >> 7;        // 0..3 (k-group of 8 floats)
    int rb = tid & 15;        // compute: row base
    int og = tid >> 4;        // compute: out base (0..31)

    if (tid < HIDD) sC[tid] = g_c[tid];

    ull acc[8][4];
    #pragma unroll
    for (int i = 0; i < 8; ++i)
        #pragma unroll
        for (int j = 0; j < 4; ++j) acc[i][j] = 0ULL;

    long long ar = row0 + lr;
    bool aval = (ar < (long long)B);
    const ulonglong2* aptr = (const ulonglong2*)(app + (aval ? ar : 0) * APP);
    const ulonglong2* wptr = (const ulonglong2*)(g_M1 + (size_t)lr * APP);
    const ulonglong2* hptr = (const ulonglong2*)(g_Hlast + (aval ? ar : 0) * H);
    const ulonglong2* mptr = (const ulonglong2*)(g_M2 + lr * H);

    // 18 K-tiles: 16 over appearance (K=512), 2 over h_last (K=64)
    #pragma unroll 1
    for (int kt = 0; kt < 18; ++kt) {
        int kof;
        ulonglong2 va0, va1, vw0, vw1;
        ulonglong2 zz; zz.x = 0ULL; zz.y = 0ULL;
        if (kt < 16) {
            kof = kt * 32 + kg * 8;
            va0 = aval ? aptr[kof / 4] : zz;
            va1 = aval ? aptr[kof / 4 + 1] : zz;
            vw0 = wptr[kof / 4];
            vw1 = wptr[kof / 4 + 1];
        } else {
            kof = (kt - 16) * 32 + kg * 8;
            va0 = aval ? hptr[kof / 4] : zz;
            va1 = aval ? hptr[kof / 4 + 1] : zz;
            vw0 = mptr[kof / 4];
            vw1 = mptr[kof / 4 + 1];
        }
        int k2b = kg * 4;
        sa[(k2b + 0) * HIDD + lr] = va0.x;
        sa[(k2b + 1) * HIDD + lr] = va0.y;
        sa[(k2b + 2) * HIDD + lr] = va1.x;
        sa[(k2b + 3) * HIDD + lr] = va1.y;
        sw[(k2b + 0) * HIDD + lr] = vw0.x;
        sw[(k2b + 1) * HIDD + lr] = vw0.y;
        sw[(k2b + 2) * HIDD + lr] = vw1.x;
        sw[(k2b + 3) * HIDD + lr] = vw1.y;
        __syncthreads();

        #pragma unroll
        for (int k2 = 0; k2 < 16; ++k2) {
            ull a2[8], w2[4];
            #pragma unroll
            for (int i = 0; i < 8; ++i) a2[i] = sa[k2 * HIDD + rb + 16 * i];
            #pragma unroll
            for (int j = 0; j < 4; ++j) w2[j] = sw[k2 * HIDD + og + 32 * j];
            #pragma unroll
            for (int i = 0; i < 8; ++i)
                #pragma unroll
                for (int j = 0; j < 4; ++j) fma2(acc[i][j], a2[i], w2[j]);
        }
        __syncthreads();
    }

    #pragma unroll
    for (int i = 0; i < 8; ++i) {
        long long r = row0 + rb + 16 * i;
        if (r < (long long)B) {
            #pragma unroll
            for (int j = 0; j < 4; ++j) {
                int o = og + 32 * j;
                float v = hsum2(acc[i][j]) + sC[o];
                out[r * HIDD + o] = 0.5f * v * (1.f + erff(v * 0.7071067811865476f));
            }
        }
    }
}

// ============================================================
extern "C" void kernel_launch(void* const* d_in, const int* in_sizes, int n_in,
                              void* d_out, int out_size) {
    const float* app  = (const float*)d_in[0];
    const float* cen  = (const float*)d_in[1];
    const float* W_ih = (const float*)d_in[2];
    const float* W_hh = (const float*)d_in[3];
    const float* b_ih = (const float*)d_in[4];
    const float* b_hh = (const float*)d_in[5];
    const float* Wt   = (const float*)d_in[6];
    const float* bt   = (const float*)d_in[7];
    const float* Wa   = (const float*)d_in[8];
    const float* ba   = (const float*)d_in[9];
    const float* Wf   = (const float*)d_in[10];
    const float* bf   = (const float*)d_in[11];
    float* out = (float*)d_out;

    int B = in_sizes[0] / APP;

    (void)cudaGetLastError();
    (void)cudaFuncSetAttribute(gru_kernel,
                               cudaFuncAttributeMaxDynamicSharedMemorySize, SMEM_GRU);

    precompute_kernel<<<289, 256>>>(Wt, bt, Wa, ba, Wf, bf);

    int gridA = (B + ROWS_A - 1) / ROWS_A;
    gru_kernel<<<gridA, TPB_A, SMEM_GRU>>>(cen, W_ih, W_hh, b_ih, b_hh, B);

    int gridB = (B + HIDD - 1) / HIDD;
    proj_kernel<<<gridB, TPB_B>>>(app, out, B);
}